// round 14
// baseline (speedup 1.0000x reference)
#include <cuda_runtime.h>
#include <cuda_bf16.h>
#include <cstdint>
#include <math.h>

#define BB 64
#define TT 512
#define DD 512
#define HH 1024
#define G4 4096
#define NBLK 128

#define WROW 2064                 // bytes per W_hh row in SMEM
#define LROWB 80                  // bytes per row in an h 32-k block (64B data + 16B pad)
#define LBLK (128 * LROWB)        // 10240 bytes per block (64 hi rows + 64 lo rows)

// ---------------- device scratch ----------------
__device__ float g_xg[(size_t)BB * TT * G4];
__device__ __align__(16) unsigned char g_hA[4][32 * LBLK];   // h, 4 parities x 32 blocks
__device__ unsigned g_ready[4][32];                          // per-parity per-block ready counters
__device__ __align__(1024) unsigned char g_xA[(size_t)256 * 8 * 32768];
__device__ __align__(1024) unsigned char g_wA[(size_t)32 * 8 * 32768];

// ---------------- helpers ----------------
__device__ __forceinline__ unsigned smem_u32(const void* p) {
    return (unsigned)__cvta_generic_to_shared(p);
}
__device__ __forceinline__ void mbar_init(unsigned a, unsigned n) {
    asm volatile("mbarrier.init.shared.b64 [%0], %1;" :: "r"(a), "r"(n) : "memory");
}
__device__ __forceinline__ void mbar_expect_tx(unsigned a, unsigned b) {
    asm volatile("mbarrier.arrive.expect_tx.shared.b64 _, [%0], %1;" :: "r"(a), "r"(b) : "memory");
}
__device__ __forceinline__ void mbar_wait(unsigned a, unsigned p) {
    asm volatile(
        "{\n\t.reg .pred P;\n"
        "W_%=:\n\t"
        "mbarrier.try_wait.parity.acquire.cta.shared::cta.b64 P, [%0], %1, 0x989680;\n\t"
        "@P bra D_%=;\n\t"
        "bra W_%=;\n"
        "D_%=:\n\t}" :: "r"(a), "r"(p) : "memory");
}
__device__ __forceinline__ void bulk_cp(void* sdst, const void* gsrc, unsigned bytes, unsigned mbar) {
    unsigned d = smem_u32(sdst);
    asm volatile(
        "cp.async.bulk.shared::cluster.global.mbarrier::complete_tx::bytes [%0], [%1], %2, [%3];"
        :: "r"(d), "l"(gsrc), "r"(bytes), "r"(mbar) : "memory");
}
__device__ __forceinline__ void mma_bf16(float* c, unsigned a0, unsigned a1, unsigned a2, unsigned a3,
                                         unsigned b0, unsigned b1) {
    asm volatile(
        "mma.sync.aligned.m16n8k16.row.col.f32.bf16.bf16.f32 "
        "{%0,%1,%2,%3}, {%4,%5,%6,%7}, {%8,%9}, {%0,%1,%2,%3};"
        : "+f"(c[0]), "+f"(c[1]), "+f"(c[2]), "+f"(c[3])
        : "r"(a0), "r"(a1), "r"(a2), "r"(a3), "r"(b0), "r"(b1));
}
__device__ __forceinline__ unsigned pack_hi(float v0, float v1, float& l0, float& l1) {
    __nv_bfloat16 h0 = __float2bfloat16_rn(v0), h1 = __float2bfloat16_rn(v1);
    l0 = v0 - __bfloat162float(h0);
    l1 = v1 - __bfloat162float(h1);
    unsigned short u0 = *(unsigned short*)&h0, u1 = *(unsigned short*)&h1;
    return (unsigned)u0 | ((unsigned)u1 << 16);
}
__device__ __forceinline__ unsigned pack_lo(float l0, float l1) {
    __nv_bfloat16 a = __float2bfloat16_rn(l0), b = __float2bfloat16_rn(l1);
    unsigned short u0 = *(unsigned short*)&a, u1 = *(unsigned short*)&b;
    return (unsigned)u0 | ((unsigned)u1 << 16);
}
__device__ __forceinline__ float sigm(float x) { return 1.f / (1.f + expf(-x)); }
__device__ __forceinline__ float fsigm(float x) { return 1.f / (1.f + __expf(-x)); }
__device__ __forceinline__ float ftanh(float x) {
    float t = __expf(-2.f * fabsf(x));
    float r = (1.f - t) / (1.f + t);
    return copysignf(r, x);
}
__device__ __forceinline__ unsigned swz(unsigned off) { return off ^ ((off >> 3) & 0x70); }
__device__ __forceinline__ unsigned sadr(int row, int slot, int tig) {
    return (unsigned)(row * 128 + ((slot ^ (row & 7)) << 4) + tig * 4);
}
__device__ __forceinline__ void flag_wait(const unsigned* f, unsigned target) {
    while (*(volatile const unsigned*)f < target) { __nanosleep(32); }
}

// ---------------- lead kernel: zero ready flags ----------------
__global__ void z0() {
    int i = threadIdx.x;
    if (i < 128) ((unsigned*)g_ready)[i] = 0u;
}

// ---------------- cvt (unchanged) ----------------
#define XN8 (BB * TT * DD / 8)
#define WN8 (G4 * DD / 8)
__global__ void cvt(const float* __restrict__ X, const float* __restrict__ Wih) {
    size_t i = (size_t)blockIdx.x * 256 + threadIdx.x;
    if (i >= XN8 + WN8) return;
    const float* src;
    unsigned char* tile;
    size_t e;
    int r, cb;
    if (i < XN8) {
        e = i * 8;
        int rg = (int)(e >> 9);
        int k = (int)(e & 511);
        tile = g_xA + ((size_t)((rg >> 7) * 8 + (k >> 6))) * 32768;
        src = X;
        r = rg & 127; cb = (k & 63) * 2;
    } else {
        e = (i - XN8) * 8;
        int ng = (int)(e >> 9);
        int k = (int)(e & 511);
        tile = g_wA + ((size_t)((ng >> 7) * 8 + (k >> 6))) * 32768;
        src = Wih;
        r = ng & 127; cb = (k & 63) * 2;
    }
    float4 v0 = *(const float4*)(src + e);
    float4 v1 = *(const float4*)(src + e + 4);
    float l0, l1, l2, l3, l4, l5, l6, l7;
    unsigned h0 = pack_hi(v0.x, v0.y, l0, l1), h1 = pack_hi(v0.z, v0.w, l2, l3);
    unsigned h2 = pack_hi(v1.x, v1.y, l4, l5), h3 = pack_hi(v1.z, v1.w, l6, l7);
    *(uint4*)(tile + swz((unsigned)(r * 128 + cb))) = make_uint4(h0, h1, h2, h3);
    *(uint4*)(tile + swz((unsigned)((r + 128) * 128 + cb))) =
        make_uint4(pack_lo(l0, l1), pack_lo(l2, l3), pack_lo(l4, l5), pack_lo(l6, l7));
}

// ---------------- xg HMMA GEMM (unchanged) ----------------
#define XBUF 65536
#define XSMEM (2 * XBUF)

__global__ __launch_bounds__(256, 1)
void xg_tc(const float* __restrict__ bih, const float* __restrict__ bhh) {
    extern __shared__ __align__(128) char xsm[];
    __shared__ __align__(8) unsigned long long xmb[2];

    int tid = threadIdx.x;
    int w = tid >> 5, lane = tid & 31;
    int g = lane >> 2, tig = lane & 3;
    int wm = w & 3, wn = w >> 2;
    int bn = blockIdx.x, bm = blockIdx.y;

    unsigned mb[2] = { smem_u32(&xmb[0]), smem_u32(&xmb[1]) };
    if (tid == 0) { mbar_init(mb[0], 1); mbar_init(mb[1], 1); }
    __syncthreads();

    const unsigned char* asrc = g_xA + (size_t)bm * 8 * 32768;
    const unsigned char* bsrc = g_wA + (size_t)bn * 8 * 32768;

    auto stage = [&](int buf, int ch) {
        if (tid == 0) {
            mbar_expect_tx(mb[buf], 65536u);
            bulk_cp(xsm + buf * XBUF, asrc + ch * 32768, 32768u, mb[buf]);
            bulk_cp(xsm + buf * XBUF + 32768, bsrc + ch * 32768, 32768u, mb[buf]);
        }
    };

    float acc[2][8][4];
#pragma unroll
    for (int mf = 0; mf < 2; mf++)
#pragma unroll
        for (int nf = 0; nf < 8; nf++)
#pragma unroll
            for (int i = 0; i < 4; i++) acc[mf][nf][i] = 0.f;

    stage(0, 0);
    stage(1, 1);
    unsigned cnt[2] = {1, 1};

    for (int ch = 0; ch < 8; ch++) {
        int buf = ch & 1;
        mbar_wait(mb[buf], (cnt[buf] - 1) & 1);
        const char* Ab = xsm + buf * XBUF;
        const char* Bb = Ab + 32768;

#pragma unroll
        for (int ks = 0; ks < 4; ks++) {
            unsigned ah[2][4], al[2][4];
#pragma unroll
            for (int mf = 0; mf < 2; mf++) {
                int rh = wm * 32 + mf * 16 + g;
                ah[mf][0] = *(const unsigned*)(Ab + sadr(rh,       ks * 2,     tig));
                ah[mf][2] = *(const unsigned*)(Ab + sadr(rh,       ks * 2 + 1, tig));
                ah[mf][1] = *(const unsigned*)(Ab + sadr(rh + 8,   ks * 2,     tig));
                ah[mf][3] = *(const unsigned*)(Ab + sadr(rh + 8,   ks * 2 + 1, tig));
                al[mf][0] = *(const unsigned*)(Ab + sadr(rh + 128, ks * 2,     tig));
                al[mf][2] = *(const unsigned*)(Ab + sadr(rh + 128, ks * 2 + 1, tig));
                al[mf][1] = *(const unsigned*)(Ab + sadr(rh + 136, ks * 2,     tig));
                al[mf][3] = *(const unsigned*)(Ab + sadr(rh + 136, ks * 2 + 1, tig));
            }
#pragma unroll
            for (int nf = 0; nf < 8; nf++) {
                int rn = wn * 64 + nf * 8 + g;
                unsigned bh0 = *(const unsigned*)(Bb + sadr(rn,       ks * 2,     tig));
                unsigned bh1 = *(const unsigned*)(Bb + sadr(rn,       ks * 2 + 1, tig));
                unsigned bl0 = *(const unsigned*)(Bb + sadr(rn + 128, ks * 2,     tig));
                unsigned bl1 = *(const unsigned*)(Bb + sadr(rn + 128, ks * 2 + 1, tig));
#pragma unroll
                for (int mf = 0; mf < 2; mf++) {
                    mma_bf16(acc[mf][nf], ah[mf][0], ah[mf][1], ah[mf][2], ah[mf][3], bh0, bh1);
                    mma_bf16(acc[mf][nf], ah[mf][0], ah[mf][1], ah[mf][2], ah[mf][3], bl0, bl1);
                    mma_bf16(acc[mf][nf], al[mf][0], al[mf][1], al[mf][2], al[mf][3], bh0, bh1);
                }
            }
        }
        __syncthreads();
        if (ch + 2 < 8) {
            stage(buf, ch + 2);
            cnt[buf]++;
        }
    }

#pragma unroll
    for (int nf = 0; nf < 8; nf++) {
        int col = bn * 128 + wn * 64 + nf * 8 + tig * 2;
        float bb0 = bih[col] + bhh[col];
        float bb1 = bih[col + 1] + bhh[col + 1];
#pragma unroll
        for (int mf = 0; mf < 2; mf++) {
            int row = bm * 128 + wm * 32 + mf * 16 + g;
            *(float2*)(g_xg + (size_t)row * G4 + col) =
                make_float2(acc[mf][nf][0] + bb0, acc[mf][nf][1] + bb1);
            *(float2*)(g_xg + (size_t)(row + 8) * G4 + col) =
                make_float2(acc[mf][nf][2] + bb0, acc[mf][nf][3] + bb1);
        }
    }
}

// ---------------- persistent HMMA LSTM: 16 warps (4 k-quarters x 4 row-groups) ----------------
#define SM_WHI (8 * LBLK)                 // 81920
#define SM_WLO (SM_WHI + 32 * WROW)
#define SM_END (SM_WHI + 64 * WROW)       // 214016
#define SMEM_BYTES (SM_END + 1024)

__global__ __launch_bounds__(512, 1)
void lstm_tc(const float* __restrict__ Whh, const int* __restrict__ mask,
             const float* __restrict__ h0, const float* __restrict__ c0,
             float* __restrict__ out) {
    extern __shared__ char smraw[];
    char* smb = (char*)(((uintptr_t)smraw + 1023) & ~(uintptr_t)1023);
    char* Whi = smb + SM_WHI;
    char* Wlo = smb + SM_WLO;
    float* stash = (float*)smb;             // aliases A buffers

    __shared__ __align__(8) unsigned long long mbst[8];

    int tid = threadIdx.x;
    int w = tid >> 5, lane = tid & 31;
    int g = lane >> 2, tig = lane & 3;
    int wk = w & 3;                          // k-quarter
    int wm4 = w >> 2;                        // row group 0..3 (16 rows each)
    int bid = blockIdx.x;
    int base = bid * 8;
    int gb_own = base >> 5;
    int koff_own = (base & 31) * 2;
    int eb = tid >> 3, eu = tid & 7;         // epilogue cell: batch row, unit

    unsigned mbw[2] = { smem_u32(&mbst[wk * 2]), smem_u32(&mbst[wk * 2 + 1]) };
    if (tid == 0)
#pragma unroll
        for (int i = 0; i < 8; i++) mbar_init(smem_u32(&mbst[i]), 1);

    // ---- build W hi/lo tiles once ----
    for (int idx = tid; idx < 32 * 128; idx += 512) {
        int n = idx >> 7, k = (idx & 127) * 8;
        int gg = n >> 3, u = n & 7;
        const float* wp = Whh + ((size_t)(gg * HH + base + u)) * HH + k;
        float4 v0 = *(const float4*)wp, v1 = *(const float4*)(wp + 4);
        float vv[8] = {v0.x, v0.y, v0.z, v0.w, v1.x, v1.y, v1.z, v1.w};
        unsigned hi4[4], lo4[4];
#pragma unroll
        for (int p = 0; p < 4; p++) {
            float l0, l1;
            hi4[p] = pack_hi(vv[2 * p], vv[2 * p + 1], l0, l1);
            lo4[p] = pack_lo(l0, l1);
        }
        *(uint4*)(Whi + (size_t)n * WROW + k * 2) = make_uint4(hi4[0], hi4[1], hi4[2], hi4[3]);
        *(uint4*)(Wlo + (size_t)n * WROW + k * 2) = make_uint4(lo4[0], lo4[1], lo4[2], lo4[3]);
    }

    // ---- per-thread state (1 cell) + initial h write (parity 0) ----
    float creg = c0[base + eu];
    float hreg = h0[base + eu];
    {
        __nv_bfloat16 hh = __float2bfloat16_rn(hreg);
        float lo = hreg - __bfloat162float(hh);
        __nv_bfloat16 hl = __float2bfloat16_rn(lo);
        unsigned char* blk = g_hA[0] + gb_own * LBLK;
        *(__nv_bfloat16*)(blk + (size_t)eb * LROWB + koff_own + eu * 2) = hh;
        *(__nv_bfloat16*)(blk + (size_t)(64 + eb) * LROWB + koff_own + eu * 2) = hl;
    }
    __syncthreads();
    if (tid == 0) {
        __threadfence();
        atomicAdd(&g_ready[0][gb_own], 1u);
    }

    unsigned cnt0 = 0, cnt1 = 0;

    for (int t = 0; t < TT; t++) {
        const unsigned char* src = g_hA[t & 3];
        unsigned rdy_target = 4u * (unsigned)(t / 4 + 1);
        const unsigned* rdy = g_ready[t & 3];

        // ---- prologue: warps 0-3 stage their quarter's first two blocks ----
        if (w < 4 && lane == 0) {
#pragma unroll
            for (int d = 0; d < 2; d++) {
                int gb = wk * 8 + d;
                flag_wait(&rdy[gb], rdy_target);
                mbar_expect_tx(mbw[d], (unsigned)LBLK);
                bulk_cp(smb + (size_t)(wk * 2 + d) * LBLK, src + (size_t)gb * LBLK, (unsigned)LBLK, mbw[d]);
            }
        }
        cnt0++; cnt1++;

        // ---- prefetch xg + mask (per epilogue cell) ----
        float xg4[4];
        {
            const float* xp = g_xg + ((size_t)eb * TT + t) * G4 + base + eu;
#pragma unroll
            for (int gg = 0; gg < 4; gg++) xg4[gg] = __ldg(xp + gg * HH);
        }
        int m = __ldg(mask + eb * TT + t);

        float acc[4][4];
#pragma unroll
        for (int nt = 0; nt < 4; nt++)
#pragma unroll
            for (int i = 0; i < 4; i++) acc[nt][i] = 0.f;

        int rowf = wm4 * 16 + g;

        // ---- per-quarter K stream: 8 blocks of 32 k, consumed by 4-warp group ----
        for (int b = 0; b < 8; b++) {
            int d = b & 1;
            mbar_wait(mbw[d], ((d ? cnt1 : cnt0) - 1) & 1);
            const char* Ab = smb + (size_t)(wk * 2 + d) * LBLK;
            int kglob = (wk * 8 + b) * 32;

#pragma unroll
            for (int ks = 0; ks < 2; ks++) {
                unsigned r0 = (unsigned)rowf * LROWB + (unsigned)(ks * 32 + tig * 4);
                unsigned ah0 = *(const unsigned*)(Ab + r0);
                unsigned ah2 = *(const unsigned*)(Ab + r0 + 16);
                unsigned ah1 = *(const unsigned*)(Ab + r0 + 8 * LROWB);
                unsigned ah3 = *(const unsigned*)(Ab + r0 + 8 * LROWB + 16);
                unsigned al0 = *(const unsigned*)(Ab + r0 + 64 * LROWB);
                unsigned al2 = *(const unsigned*)(Ab + r0 + 64 * LROWB + 16);
                unsigned al1 = *(const unsigned*)(Ab + r0 + 72 * LROWB);
                unsigned al3 = *(const unsigned*)(Ab + r0 + 72 * LROWB + 16);
                unsigned kb = (unsigned)((kglob + ks * 16 + tig * 2) * 2);
#pragma unroll
                for (int nt = 0; nt < 4; nt++) {
                    const char* wh = Whi + (size_t)(nt * 8 + g) * WROW + kb;
                    const char* wl = Wlo + (size_t)(nt * 8 + g) * WROW + kb;
                    unsigned bh0 = *(const unsigned*)wh;
                    unsigned bh1 = *(const unsigned*)(wh + 16);
                    unsigned bl0 = *(const unsigned*)wl;
                    unsigned bl1 = *(const unsigned*)(wl + 16);
                    mma_bf16(acc[nt], ah0, ah1, ah2, ah3, bh0, bh1);
                    mma_bf16(acc[nt], ah0, ah1, ah2, ah3, bl0, bl1);
                    mma_bf16(acc[nt], al0, al1, al2, al3, bh0, bh1);
                }
            }

            // group barrier: all 4 consumer warps of this quarter done with buffer d
            asm volatile("bar.sync %0, 128;" :: "r"(1 + wk) : "memory");

            if (b + 2 < 8) {
                if (w < 4 && lane == 0) {
                    int gb = wk * 8 + b + 2;
                    flag_wait(&rdy[gb], rdy_target);
                    mbar_expect_tx(mbw[d], (unsigned)LBLK);
                    bulk_cp(smb + (size_t)(wk * 2 + d) * LBLK, src + (size_t)gb * LBLK, (unsigned)LBLK, mbw[d]);
                }
                if (d) cnt1++; else cnt0++;
            }
        }

        // ---- cross-warp reduction via stash (aliases buffers: sync first) ----
        __syncthreads();
#pragma unroll
        for (int nt = 0; nt < 4; nt++) {
            int c = nt * 8 + tig * 2;
            *(float2*)&stash[((size_t)wk * 64 + rowf) * 34 + c] =
                make_float2(acc[nt][0], acc[nt][1]);
            *(float2*)&stash[((size_t)wk * 64 + rowf + 8) * 34 + c] =
                make_float2(acc[nt][2], acc[nt][3]);
        }
        __syncthreads();

        // ---- epilogue: 1 cell per thread, fast math ----
        {
            float gi = xg4[0], gf = xg4[1], gG = xg4[2], go = xg4[3];
#pragma unroll
            for (int ww = 0; ww < 4; ww++) {
                const float* sp = stash + ((size_t)ww * 64 + eb) * 34;
                gi += sp[eu];
                gf += sp[8 + eu];
                gG += sp[16 + eu];
                go += sp[24 + eu];
            }
            float iv = fsigm(gi);
            float fv = fsigm(gf);
            float gv = ftanh(gG);
            float ov = fsigm(go);
            float cn = fv * creg + iv * gv;
            float hn = ov * ftanh(cn);
            creg = m ? cn : creg;
            hn   = m ? hn : hreg;
            hreg = hn;
            out[((size_t)eb * TT + t) * HH + base + eu] = hn;
            __nv_bfloat16 hh = __float2bfloat16_rn(hn);
            float lo = hn - __bfloat162float(hh);
            __nv_bfloat16 hl = __float2bfloat16_rn(lo);
            unsigned char* blk = g_hA[(t + 1) & 3] + gb_own * LBLK;
            *(__nv_bfloat16*)(blk + (size_t)eb * LROWB + koff_own + eu * 2) = hh;
            *(__nv_bfloat16*)(blk + (size_t)(64 + eb) * LROWB + koff_own + eu * 2) = hl;
        }

        // ---- post readiness of this CTA's slice of h(t+1) ----
        __syncthreads();
        if (tid == 0) {
            __threadfence();
            atomicAdd(&g_ready[(t + 1) & 3][gb_own], 1u);
        }
    }
}

// ---------------- launch ----------------
extern "C" void kernel_launch(void* const* d_in, const int* in_sizes, int n_in,
                              void* d_out, int out_size) {
    const float* x    = (const float*)d_in[0];
    const int*   mask = (const int*)  d_in[1];
    const float* Wih  = (const float*)d_in[2];
    const float* Whh  = (const float*)d_in[3];
    const float* bih  = (const float*)d_in[4];
    const float* bhh  = (const float*)d_in[5];
    const float* h0   = (const float*)d_in[6];
    const float* c0   = (const float*)d_in[7];
    float* out = (float*)d_out;

    cudaFuncSetAttribute(xg_tc, cudaFuncAttributeMaxDynamicSharedMemorySize, XSMEM);
    cudaFuncSetAttribute(lstm_tc, cudaFuncAttributeMaxDynamicSharedMemorySize, SMEM_BYTES);

    z0<<<1, 128>>>();
    cvt<<<(XN8 + WN8 + 255) / 256, 256>>>(x, Wih);
    xg_tc<<<dim3(G4 / 128, (BB * TT) / 128), 256, XSMEM>>>(bih, bhh);
    lstm_tc<<<NBLK, 512, SMEM_BYTES>>>(Whh, mask, h0, c0, out);
}

// round 15
// speedup vs baseline: 1.0589x; 1.0589x over previous
#include <cuda_runtime.h>
#include <cuda_bf16.h>
#include <cstdint>
#include <math.h>

#define BB 64
#define TT 512
#define DD 512
#define HH 1024
#define G4 4096
#define NBLK 128

#define WROW 2064                 // bytes per W_hh row in SMEM
#define LROWB 80                  // bytes per row in an h 32-k block (64B data + 16B pad)
#define LBLK (128 * LROWB)        // 10240 bytes per block (64 hi rows + 64 lo rows)

// ---------------- device scratch ----------------
__device__ float g_xg[(size_t)BB * TT * G4];
__device__ __align__(16) unsigned char g_hA[4][32 * LBLK];   // h, 4 parities x 32 blocks
__device__ unsigned g_ready[4][32];                          // per-parity per-block ready counters
__device__ __align__(1024) unsigned char g_xA[(size_t)256 * 8 * 32768];
__device__ __align__(1024) unsigned char g_wA[(size_t)32 * 8 * 32768];

// ---------------- helpers ----------------
__device__ __forceinline__ unsigned smem_u32(const void* p) {
    return (unsigned)__cvta_generic_to_shared(p);
}
__device__ __forceinline__ void mbar_init(unsigned a, unsigned n) {
    asm volatile("mbarrier.init.shared.b64 [%0], %1;" :: "r"(a), "r"(n) : "memory");
}
__device__ __forceinline__ void mbar_expect_tx(unsigned a, unsigned b) {
    asm volatile("mbarrier.arrive.expect_tx.shared.b64 _, [%0], %1;" :: "r"(a), "r"(b) : "memory");
}
__device__ __forceinline__ void mbar_arrive(unsigned a) {
    asm volatile("mbarrier.arrive.shared.b64 _, [%0];" :: "r"(a) : "memory");
}
__device__ __forceinline__ void mbar_wait(unsigned a, unsigned p) {
    asm volatile(
        "{\n\t.reg .pred P;\n"
        "W_%=:\n\t"
        "mbarrier.try_wait.parity.acquire.cta.shared::cta.b64 P, [%0], %1, 0x989680;\n\t"
        "@P bra D_%=;\n\t"
        "bra W_%=;\n"
        "D_%=:\n\t}" :: "r"(a), "r"(p) : "memory");
}
__device__ __forceinline__ void bulk_cp(void* sdst, const void* gsrc, unsigned bytes, unsigned mbar) {
    unsigned d = smem_u32(sdst);
    asm volatile(
        "cp.async.bulk.shared::cluster.global.mbarrier::complete_tx::bytes [%0], [%1], %2, [%3];"
        :: "r"(d), "l"(gsrc), "r"(bytes), "r"(mbar) : "memory");
}
__device__ __forceinline__ void mma_bf16(float* c, unsigned a0, unsigned a1, unsigned a2, unsigned a3,
                                         unsigned b0, unsigned b1) {
    asm volatile(
        "mma.sync.aligned.m16n8k16.row.col.f32.bf16.bf16.f32 "
        "{%0,%1,%2,%3}, {%4,%5,%6,%7}, {%8,%9}, {%0,%1,%2,%3};"
        : "+f"(c[0]), "+f"(c[1]), "+f"(c[2]), "+f"(c[3])
        : "r"(a0), "r"(a1), "r"(a2), "r"(a3), "r"(b0), "r"(b1));
}
__device__ __forceinline__ unsigned pack_hi(float v0, float v1, float& l0, float& l1) {
    __nv_bfloat16 h0 = __float2bfloat16_rn(v0), h1 = __float2bfloat16_rn(v1);
    l0 = v0 - __bfloat162float(h0);
    l1 = v1 - __bfloat162float(h1);
    unsigned short u0 = *(unsigned short*)&h0, u1 = *(unsigned short*)&h1;
    return (unsigned)u0 | ((unsigned)u1 << 16);
}
__device__ __forceinline__ unsigned pack_lo(float l0, float l1) {
    __nv_bfloat16 a = __float2bfloat16_rn(l0), b = __float2bfloat16_rn(l1);
    unsigned short u0 = *(unsigned short*)&a, u1 = *(unsigned short*)&b;
    return (unsigned)u0 | ((unsigned)u1 << 16);
}
__device__ __forceinline__ float fsigm(float x) { return 1.f / (1.f + __expf(-x)); }
__device__ __forceinline__ float ftanh(float x) {
    float t = __expf(-2.f * fabsf(x));
    float r = (1.f - t) / (1.f + t);
    return copysignf(r, x);
}
__device__ __forceinline__ unsigned swz(unsigned off) { return off ^ ((off >> 3) & 0x70); }
__device__ __forceinline__ unsigned sadr(int row, int slot, int tig) {
    return (unsigned)(row * 128 + ((slot ^ (row & 7)) << 4) + tig * 4);
}
__device__ __forceinline__ void flag_wait(const unsigned* f, unsigned target) {
    while (*(volatile const unsigned*)f < target) { __nanosleep(32); }
}

// ---------------- lead kernel: zero ready flags ----------------
__global__ void z0() {
    int i = threadIdx.x;
    if (i < 128) ((unsigned*)g_ready)[i] = 0u;
}

// ---------------- cvt (unchanged) ----------------
#define XN8 (BB * TT * DD / 8)
#define WN8 (G4 * DD / 8)
__global__ void cvt(const float* __restrict__ X, const float* __restrict__ Wih) {
    size_t i = (size_t)blockIdx.x * 256 + threadIdx.x;
    if (i >= XN8 + WN8) return;
    const float* src;
    unsigned char* tile;
    size_t e;
    int r, cb;
    if (i < XN8) {
        e = i * 8;
        int rg = (int)(e >> 9);
        int k = (int)(e & 511);
        tile = g_xA + ((size_t)((rg >> 7) * 8 + (k >> 6))) * 32768;
        src = X;
        r = rg & 127; cb = (k & 63) * 2;
    } else {
        e = (i - XN8) * 8;
        int ng = (int)(e >> 9);
        int k = (int)(e & 511);
        tile = g_wA + ((size_t)((ng >> 7) * 8 + (k >> 6))) * 32768;
        src = Wih;
        r = ng & 127; cb = (k & 63) * 2;
    }
    float4 v0 = *(const float4*)(src + e);
    float4 v1 = *(const float4*)(src + e + 4);
    float l0, l1, l2, l3, l4, l5, l6, l7;
    unsigned h0 = pack_hi(v0.x, v0.y, l0, l1), h1 = pack_hi(v0.z, v0.w, l2, l3);
    unsigned h2 = pack_hi(v1.x, v1.y, l4, l5), h3 = pack_hi(v1.z, v1.w, l6, l7);
    *(uint4*)(tile + swz((unsigned)(r * 128 + cb))) = make_uint4(h0, h1, h2, h3);
    *(uint4*)(tile + swz((unsigned)((r + 128) * 128 + cb))) =
        make_uint4(pack_lo(l0, l1), pack_lo(l2, l3), pack_lo(l4, l5), pack_lo(l6, l7));
}

// ---------------- xg HMMA GEMM (unchanged) ----------------
#define XBUF 65536
#define XSMEM (2 * XBUF)

__global__ __launch_bounds__(256, 1)
void xg_tc(const float* __restrict__ bih, const float* __restrict__ bhh) {
    extern __shared__ __align__(128) char xsm[];
    __shared__ __align__(8) unsigned long long xmb[2];

    int tid = threadIdx.x;
    int w = tid >> 5, lane = tid & 31;
    int g = lane >> 2, tig = lane & 3;
    int wm = w & 3, wn = w >> 2;
    int bn = blockIdx.x, bm = blockIdx.y;

    unsigned mb[2] = { smem_u32(&xmb[0]), smem_u32(&xmb[1]) };
    if (tid == 0) { mbar_init(mb[0], 1); mbar_init(mb[1], 1); }
    __syncthreads();

    const unsigned char* asrc = g_xA + (size_t)bm * 8 * 32768;
    const unsigned char* bsrc = g_wA + (size_t)bn * 8 * 32768;

    auto stage = [&](int buf, int ch) {
        if (tid == 0) {
            mbar_expect_tx(mb[buf], 65536u);
            bulk_cp(xsm + buf * XBUF, asrc + ch * 32768, 32768u, mb[buf]);
            bulk_cp(xsm + buf * XBUF + 32768, bsrc + ch * 32768, 32768u, mb[buf]);
        }
    };

    float acc[2][8][4];
#pragma unroll
    for (int mf = 0; mf < 2; mf++)
#pragma unroll
        for (int nf = 0; nf < 8; nf++)
#pragma unroll
            for (int i = 0; i < 4; i++) acc[mf][nf][i] = 0.f;

    stage(0, 0);
    stage(1, 1);
    unsigned cnt[2] = {1, 1};

    for (int ch = 0; ch < 8; ch++) {
        int buf = ch & 1;
        mbar_wait(mb[buf], (cnt[buf] - 1) & 1);
        const char* Ab = xsm + buf * XBUF;
        const char* Bb = Ab + 32768;

#pragma unroll
        for (int ks = 0; ks < 4; ks++) {
            unsigned ah[2][4], al[2][4];
#pragma unroll
            for (int mf = 0; mf < 2; mf++) {
                int rh = wm * 32 + mf * 16 + g;
                ah[mf][0] = *(const unsigned*)(Ab + sadr(rh,       ks * 2,     tig));
                ah[mf][2] = *(const unsigned*)(Ab + sadr(rh,       ks * 2 + 1, tig));
                ah[mf][1] = *(const unsigned*)(Ab + sadr(rh + 8,   ks * 2,     tig));
                ah[mf][3] = *(const unsigned*)(Ab + sadr(rh + 8,   ks * 2 + 1, tig));
                al[mf][0] = *(const unsigned*)(Ab + sadr(rh + 128, ks * 2,     tig));
                al[mf][2] = *(const unsigned*)(Ab + sadr(rh + 128, ks * 2 + 1, tig));
                al[mf][1] = *(const unsigned*)(Ab + sadr(rh + 136, ks * 2,     tig));
                al[mf][3] = *(const unsigned*)(Ab + sadr(rh + 136, ks * 2 + 1, tig));
            }
#pragma unroll
            for (int nf = 0; nf < 8; nf++) {
                int rn = wn * 64 + nf * 8 + g;
                unsigned bh0 = *(const unsigned*)(Bb + sadr(rn,       ks * 2,     tig));
                unsigned bh1 = *(const unsigned*)(Bb + sadr(rn,       ks * 2 + 1, tig));
                unsigned bl0 = *(const unsigned*)(Bb + sadr(rn + 128, ks * 2,     tig));
                unsigned bl1 = *(const unsigned*)(Bb + sadr(rn + 128, ks * 2 + 1, tig));
#pragma unroll
                for (int mf = 0; mf < 2; mf++) {
                    mma_bf16(acc[mf][nf], ah[mf][0], ah[mf][1], ah[mf][2], ah[mf][3], bh0, bh1);
                    mma_bf16(acc[mf][nf], ah[mf][0], ah[mf][1], ah[mf][2], ah[mf][3], bl0, bl1);
                    mma_bf16(acc[mf][nf], al[mf][0], al[mf][1], al[mf][2], al[mf][3], bh0, bh1);
                }
            }
        }
        __syncthreads();
        if (ch + 2 < 8) {
            stage(buf, ch + 2);
            cnt[buf]++;
        }
    }

#pragma unroll
    for (int nf = 0; nf < 8; nf++) {
        int col = bn * 128 + wn * 64 + nf * 8 + tig * 2;
        float bb0 = bih[col] + bhh[col];
        float bb1 = bih[col + 1] + bhh[col + 1];
#pragma unroll
        for (int mf = 0; mf < 2; mf++) {
            int row = bm * 128 + wm * 32 + mf * 16 + g;
            *(float2*)(g_xg + (size_t)row * G4 + col) =
                make_float2(acc[mf][nf][0] + bb0, acc[mf][nf][1] + bb1);
            *(float2*)(g_xg + (size_t)(row + 8) * G4 + col) =
                make_float2(acc[mf][nf][2] + bb0, acc[mf][nf][3] + bb1);
        }
    }
}

// ---------------- persistent HMMA LSTM: full/empty mbarrier pipeline ----------------
#define SM_WHI (8 * LBLK)                 // 81920
#define SM_WLO (SM_WHI + 32 * WROW)
#define SM_END (SM_WHI + 64 * WROW)       // 214016
#define SMEM_BYTES (SM_END + 1024)

__global__ __launch_bounds__(512, 1)
void lstm_tc(const float* __restrict__ Whh, const int* __restrict__ mask,
             const float* __restrict__ h0, const float* __restrict__ c0,
             float* __restrict__ out) {
    extern __shared__ char smraw[];
    char* smb = (char*)(((uintptr_t)smraw + 1023) & ~(uintptr_t)1023);
    char* Whi = smb + SM_WHI;
    char* Wlo = smb + SM_WLO;
    float* stash = (float*)smb;             // aliases A buffers

    __shared__ __align__(8) unsigned long long mbst[16];   // 0-7 full, 8-15 empty

    int tid = threadIdx.x;
    int w = tid >> 5, lane = tid & 31;
    int g = lane >> 2, tig = lane & 3;
    int wk = w & 3;                          // k-quarter
    int wm4 = w >> 2;                        // row group 0..3
    int bid = blockIdx.x;
    int base = bid * 8;
    int gb_own = base >> 5;
    int koff_own = (base & 31) * 2;
    int eb = tid >> 3, eu = tid & 7;         // epilogue cell

    unsigned mbF[2] = { smem_u32(&mbst[wk * 2]),     smem_u32(&mbst[wk * 2 + 1]) };
    unsigned mbE[2] = { smem_u32(&mbst[8 + wk * 2]), smem_u32(&mbst[8 + wk * 2 + 1]) };
    if (tid == 0) {
#pragma unroll
        for (int i = 0; i < 8; i++)  mbar_init(smem_u32(&mbst[i]), 1);   // full (expect_tx)
#pragma unroll
        for (int i = 8; i < 16; i++) mbar_init(smem_u32(&mbst[i]), 4);   // empty: 4 consumer warps
    }

    // ---- build W hi/lo tiles once ----
    for (int idx = tid; idx < 32 * 128; idx += 512) {
        int n = idx >> 7, k = (idx & 127) * 8;
        int gg = n >> 3, u = n & 7;
        const float* wp = Whh + ((size_t)(gg * HH + base + u)) * HH + k;
        float4 v0 = *(const float4*)wp, v1 = *(const float4*)(wp + 4);
        float vv[8] = {v0.x, v0.y, v0.z, v0.w, v1.x, v1.y, v1.z, v1.w};
        unsigned hi4[4], lo4[4];
#pragma unroll
        for (int p = 0; p < 4; p++) {
            float l0, l1;
            hi4[p] = pack_hi(vv[2 * p], vv[2 * p + 1], l0, l1);
            lo4[p] = pack_lo(l0, l1);
        }
        *(uint4*)(Whi + (size_t)n * WROW + k * 2) = make_uint4(hi4[0], hi4[1], hi4[2], hi4[3]);
        *(uint4*)(Wlo + (size_t)n * WROW + k * 2) = make_uint4(lo4[0], lo4[1], lo4[2], lo4[3]);
    }

    // ---- per-thread state (1 cell) + initial h write (parity 0) ----
    float creg = c0[base + eu];
    float hreg = h0[base + eu];
    {
        __nv_bfloat16 hh = __float2bfloat16_rn(hreg);
        float lo = hreg - __bfloat162float(hh);
        __nv_bfloat16 hl = __float2bfloat16_rn(lo);
        unsigned char* blk = g_hA[0] + gb_own * LBLK;
        *(__nv_bfloat16*)(blk + (size_t)eb * LROWB + koff_own + eu * 2) = hh;
        *(__nv_bfloat16*)(blk + (size_t)(64 + eb) * LROWB + koff_own + eu * 2) = hl;
    }
    __syncthreads();
    if (tid == 0) {
        __threadfence();
        atomicAdd(&g_ready[0][gb_own], 1u);
    }

    unsigned ccnt[2] = {0, 0};   // per-warp consumption counters
    unsigned fcnt[2] = {0, 0};   // producer fill counters (warps 0-3, lane 0)

    for (int t = 0; t < TT; t++) {
        const unsigned char* src = g_hA[t & 3];
        unsigned rdy_target = 4u * (unsigned)(t / 4 + 1);
        const unsigned* rdy = g_ready[t & 3];

        // ---- prologue: warps 0-3 stage their quarter's first two blocks ----
        if (w < 4 && lane == 0) {
#pragma unroll
            for (int d = 0; d < 2; d++) {
                int gb = wk * 8 + d;
                flag_wait(&rdy[gb], rdy_target);
                if (fcnt[d]) mbar_wait(mbE[d], (fcnt[d] - 1) & 1);
                mbar_expect_tx(mbF[d], (unsigned)LBLK);
                bulk_cp(smb + (size_t)(wk * 2 + d) * LBLK, src + (size_t)gb * LBLK, (unsigned)LBLK, mbF[d]);
                fcnt[d]++;
            }
        }

        // ---- prefetch xg + mask (per epilogue cell) ----
        float xg4[4];
        {
            const float* xp = g_xg + ((size_t)eb * TT + t) * G4 + base + eu;
#pragma unroll
            for (int gg = 0; gg < 4; gg++) xg4[gg] = __ldg(xp + gg * HH);
        }
        int m = __ldg(mask + eb * TT + t);

        float acc[4][4];
#pragma unroll
        for (int nt = 0; nt < 4; nt++)
#pragma unroll
            for (int i = 0; i < 4; i++) acc[nt][i] = 0.f;

        int rowf = wm4 * 16 + g;

        // ---- per-quarter K stream: consumers never rendezvous ----
        for (int b = 0; b < 8; b++) {
            int d = b & 1;
            mbar_wait(mbF[d], ccnt[d] & 1);
            ccnt[d]++;
            const char* Ab = smb + (size_t)(wk * 2 + d) * LBLK;
            int kglob = (wk * 8 + b) * 32;

#pragma unroll
            for (int ks = 0; ks < 2; ks++) {
                unsigned r0 = (unsigned)rowf * LROWB + (unsigned)(ks * 32 + tig * 4);
                unsigned ah0 = *(const unsigned*)(Ab + r0);
                unsigned ah2 = *(const unsigned*)(Ab + r0 + 16);
                unsigned ah1 = *(const unsigned*)(Ab + r0 + 8 * LROWB);
                unsigned ah3 = *(const unsigned*)(Ab + r0 + 8 * LROWB + 16);
                unsigned al0 = *(const unsigned*)(Ab + r0 + 64 * LROWB);
                unsigned al2 = *(const unsigned*)(Ab + r0 + 64 * LROWB + 16);
                unsigned al1 = *(const unsigned*)(Ab + r0 + 72 * LROWB);
                unsigned al3 = *(const unsigned*)(Ab + r0 + 72 * LROWB + 16);
                unsigned kb = (unsigned)((kglob + ks * 16 + tig * 2) * 2);
#pragma unroll
                for (int nt = 0; nt < 4; nt++) {
                    const char* wh = Whi + (size_t)(nt * 8 + g) * WROW + kb;
                    const char* wl = Wlo + (size_t)(nt * 8 + g) * WROW + kb;
                    unsigned bh0 = *(const unsigned*)wh;
                    unsigned bh1 = *(const unsigned*)(wh + 16);
                    unsigned bl0 = *(const unsigned*)wl;
                    unsigned bl1 = *(const unsigned*)(wl + 16);
                    mma_bf16(acc[nt], ah0, ah1, ah2, ah3, bh0, bh1);
                    mma_bf16(acc[nt], ah0, ah1, ah2, ah3, bl0, bl1);
                    mma_bf16(acc[nt], al0, al1, al2, al3, bh0, bh1);
                }
            }

            // consumer signals buffer free (all this round's LDS completed before last MMA issued)
            if (lane == 0) mbar_arrive(mbE[d]);

            if (b + 2 < 8) {
                if (w < 4 && lane == 0) {
                    int gb = wk * 8 + b + 2;
                    flag_wait(&rdy[gb], rdy_target);
                    mbar_wait(mbE[d], (fcnt[d] - 1) & 1);
                    mbar_expect_tx(mbF[d], (unsigned)LBLK);
                    bulk_cp(smb + (size_t)(wk * 2 + d) * LBLK, src + (size_t)gb * LBLK, (unsigned)LBLK, mbF[d]);
                    fcnt[d]++;
                }
            }
        }

        // ---- cross-warp reduction via stash (aliases buffers: sync first) ----
        __syncthreads();
#pragma unroll
        for (int nt = 0; nt < 4; nt++) {
            int c = nt * 8 + tig * 2;
            *(float2*)&stash[((size_t)wk * 64 + rowf) * 34 + c] =
                make_float2(acc[nt][0], acc[nt][1]);
            *(float2*)&stash[((size_t)wk * 64 + rowf + 8) * 34 + c] =
                make_float2(acc[nt][2], acc[nt][3]);
        }
        __syncthreads();

        // ---- epilogue: 1 cell per thread, fast math ----
        {
            float gi = xg4[0], gf = xg4[1], gG = xg4[2], go = xg4[3];
#pragma unroll
            for (int ww = 0; ww < 4; ww++) {
                const float* sp = stash + ((size_t)ww * 64 + eb) * 34;
                gi += sp[eu];
                gf += sp[8 + eu];
                gG += sp[16 + eu];
                go += sp[24 + eu];
            }
            float iv = fsigm(gi);
            float fv = fsigm(gf);
            float gv = ftanh(gG);
            float ov = fsigm(go);
            float cn = fv * creg + iv * gv;
            float hn = ov * ftanh(cn);
            creg = m ? cn : creg;
            hn   = m ? hn : hreg;
            hreg = hn;
            out[((size_t)eb * TT + t) * HH + base + eu] = hn;
            __nv_bfloat16 hh = __float2bfloat16_rn(hn);
            float lo = hn - __bfloat162float(hh);
            __nv_bfloat16 hl = __float2bfloat16_rn(lo);
            unsigned char* blk = g_hA[(t + 1) & 3] + gb_own * LBLK;
            *(__nv_bfloat16*)(blk + (size_t)eb * LROWB + koff_own + eu * 2) = hh;
            *(__nv_bfloat16*)(blk + (size_t)(64 + eb) * LROWB + koff_own + eu * 2) = hl;
        }

        // ---- post readiness of this CTA's slice of h(t+1) ----
        __syncthreads();
        if (tid == 0) {
            __threadfence();
            atomicAdd(&g_ready[(t + 1) & 3][gb_own], 1u);
        }
    }
}

// ---------------- launch ----------------
extern "C" void kernel_launch(void* const* d_in, const int* in_sizes, int n_in,
                              void* d_out, int out_size) {
    const float* x    = (const float*)d_in[0];
    const int*   mask = (const int*)  d_in[1];
    const float* Wih  = (const float*)d_in[2];
    const float* Whh  = (const float*)d_in[3];
    const float* bih  = (const float*)d_in[4];
    const float* bhh  = (const float*)d_in[5];
    const float* h0   = (const float*)d_in[6];
    const float* c0   = (const float*)d_in[7];
    float* out = (float*)d_out;

    cudaFuncSetAttribute(xg_tc, cudaFuncAttributeMaxDynamicSharedMemorySize, XSMEM);
    cudaFuncSetAttribute(lstm_tc, cudaFuncAttributeMaxDynamicSharedMemorySize, SMEM_BYTES);

    z0<<<1, 128>>>();
    cvt<<<(XN8 + WN8 + 255) / 256, 256>>>(x, Wih);
    xg_tc<<<dim3(G4 / 128, (BB * TT) / 128), 256, XSMEM>>>(bih, bhh);
    lstm_tc<<<NBLK, 512, SMEM_BYTES>>>(Whh, mask, h0, c0, out);
}

// round 16
// speedup vs baseline: 1.2552x; 1.1853x over previous
#include <cuda_runtime.h>
#include <cuda_bf16.h>
#include <cstdint>
#include <math.h>

#define BB 64
#define TT 512
#define DD 512
#define HH 1024
#define G4 4096
#define NBLK 128

#define LBLK 8192                 // dense h block: 16 tiles x 512B (4 rowgroups x 2 planes x 2 ks)

// ---------------- device scratch ----------------
__device__ float g_xg[(size_t)BB * TT * G4];
__device__ __align__(1024) unsigned char g_hA[4][32 * LBLK]; // h, 4 parities x 32 blocks (frag order)
__device__ unsigned g_ready[4][32];
__device__ __align__(1024) unsigned char g_xA[(size_t)256 * 8 * 32768];
__device__ __align__(1024) unsigned char g_wA[(size_t)32 * 8 * 32768];

// ---------------- helpers ----------------
__device__ __forceinline__ unsigned smem_u32(const void* p) {
    return (unsigned)__cvta_generic_to_shared(p);
}
__device__ __forceinline__ void mbar_init(unsigned a, unsigned n) {
    asm volatile("mbarrier.init.shared.b64 [%0], %1;" :: "r"(a), "r"(n) : "memory");
}
__device__ __forceinline__ void mbar_expect_tx(unsigned a, unsigned b) {
    asm volatile("mbarrier.arrive.expect_tx.shared.b64 _, [%0], %1;" :: "r"(a), "r"(b) : "memory");
}
__device__ __forceinline__ void mbar_arrive(unsigned a) {
    asm volatile("mbarrier.arrive.shared.b64 _, [%0];" :: "r"(a) : "memory");
}
__device__ __forceinline__ void mbar_wait(unsigned a, unsigned p) {
    asm volatile(
        "{\n\t.reg .pred P;\n"
        "W_%=:\n\t"
        "mbarrier.try_wait.parity.acquire.cta.shared::cta.b64 P, [%0], %1, 0x989680;\n\t"
        "@P bra D_%=;\n\t"
        "bra W_%=;\n"
        "D_%=:\n\t}" :: "r"(a), "r"(p) : "memory");
}
__device__ __forceinline__ void bulk_cp(void* sdst, const void* gsrc, unsigned bytes, unsigned mbar) {
    unsigned d = smem_u32(sdst);
    asm volatile(
        "cp.async.bulk.shared::cluster.global.mbarrier::complete_tx::bytes [%0], [%1], %2, [%3];"
        :: "r"(d), "l"(gsrc), "r"(bytes), "r"(mbar) : "memory");
}
__device__ __forceinline__ void mma_bf16(float* c, unsigned a0, unsigned a1, unsigned a2, unsigned a3,
                                         unsigned b0, unsigned b1) {
    asm volatile(
        "mma.sync.aligned.m16n8k16.row.col.f32.bf16.bf16.f32 "
        "{%0,%1,%2,%3}, {%4,%5,%6,%7}, {%8,%9}, {%0,%1,%2,%3};"
        : "+f"(c[0]), "+f"(c[1]), "+f"(c[2]), "+f"(c[3])
        : "r"(a0), "r"(a1), "r"(a2), "r"(a3), "r"(b0), "r"(b1));
}
__device__ __forceinline__ unsigned pack_hi(float v0, float v1, float& l0, float& l1) {
    __nv_bfloat16 h0 = __float2bfloat16_rn(v0), h1 = __float2bfloat16_rn(v1);
    l0 = v0 - __bfloat162float(h0);
    l1 = v1 - __bfloat162float(h1);
    unsigned short u0 = *(unsigned short*)&h0, u1 = *(unsigned short*)&h1;
    return (unsigned)u0 | ((unsigned)u1 << 16);
}
__device__ __forceinline__ unsigned pack_lo(float l0, float l1) {
    __nv_bfloat16 a = __float2bfloat16_rn(l0), b = __float2bfloat16_rn(l1);
    unsigned short u0 = *(unsigned short*)&a, u1 = *(unsigned short*)&b;
    return (unsigned)u0 | ((unsigned)u1 << 16);
}
__device__ __forceinline__ float fsigm(float x) { return 1.f / (1.f + __expf(-x)); }
__device__ __forceinline__ float ftanh(float x) {
    float t = __expf(-2.f * fabsf(x));
    float r = (1.f - t) / (1.f + t);
    return copysignf(r, x);
}
__device__ __forceinline__ unsigned swz(unsigned off) { return off ^ ((off >> 3) & 0x70); }
__device__ __forceinline__ unsigned sadr(int row, int slot, int tig) {
    return (unsigned)(row * 128 + ((slot ^ (row & 7)) << 4) + tig * 4);
}
__device__ __forceinline__ void flag_wait(const unsigned* f, unsigned target) {
    while (*(volatile const unsigned*)f < target) { __nanosleep(32); }
}

// ---------------- lead kernel: zero ready flags ----------------
__global__ void z0() {
    int i = threadIdx.x;
    if (i < 128) ((unsigned*)g_ready)[i] = 0u;
}

// ---------------- cvt (unchanged) ----------------
#define XN8 (BB * TT * DD / 8)
#define WN8 (G4 * DD / 8)
__global__ void cvt(const float* __restrict__ X, const float* __restrict__ Wih) {
    size_t i = (size_t)blockIdx.x * 256 + threadIdx.x;
    if (i >= XN8 + WN8) return;
    const float* src;
    unsigned char* tile;
    size_t e;
    int r, cb;
    if (i < XN8) {
        e = i * 8;
        int rg = (int)(e >> 9);
        int k = (int)(e & 511);
        tile = g_xA + ((size_t)((rg >> 7) * 8 + (k >> 6))) * 32768;
        src = X;
        r = rg & 127; cb = (k & 63) * 2;
    } else {
        e = (i - XN8) * 8;
        int ng = (int)(e >> 9);
        int k = (int)(e & 511);
        tile = g_wA + ((size_t)((ng >> 7) * 8 + (k >> 6))) * 32768;
        src = Wih;
        r = ng & 127; cb = (k & 63) * 2;
    }
    float4 v0 = *(const float4*)(src + e);
    float4 v1 = *(const float4*)(src + e + 4);
    float l0, l1, l2, l3, l4, l5, l6, l7;
    unsigned h0 = pack_hi(v0.x, v0.y, l0, l1), h1 = pack_hi(v0.z, v0.w, l2, l3);
    unsigned h2 = pack_hi(v1.x, v1.y, l4, l5), h3 = pack_hi(v1.z, v1.w, l6, l7);
    *(uint4*)(tile + swz((unsigned)(r * 128 + cb))) = make_uint4(h0, h1, h2, h3);
    *(uint4*)(tile + swz((unsigned)((r + 128) * 128 + cb))) =
        make_uint4(pack_lo(l0, l1), pack_lo(l2, l3), pack_lo(l4, l5), pack_lo(l6, l7));
}

// ---------------- xg HMMA GEMM (unchanged) ----------------
#define XBUF 65536
#define XSMEM (2 * XBUF)

__global__ __launch_bounds__(256, 1)
void xg_tc(const float* __restrict__ bih, const float* __restrict__ bhh) {
    extern __shared__ __align__(128) char xsm[];
    __shared__ __align__(8) unsigned long long xmb[2];

    int tid = threadIdx.x;
    int w = tid >> 5, lane = tid & 31;
    int g = lane >> 2, tig = lane & 3;
    int wm = w & 3, wn = w >> 2;
    int bn = blockIdx.x, bm = blockIdx.y;

    unsigned mb[2] = { smem_u32(&xmb[0]), smem_u32(&xmb[1]) };
    if (tid == 0) { mbar_init(mb[0], 1); mbar_init(mb[1], 1); }
    __syncthreads();

    const unsigned char* asrc = g_xA + (size_t)bm * 8 * 32768;
    const unsigned char* bsrc = g_wA + (size_t)bn * 8 * 32768;

    auto stage = [&](int buf, int ch) {
        if (tid == 0) {
            mbar_expect_tx(mb[buf], 65536u);
            bulk_cp(xsm + buf * XBUF, asrc + ch * 32768, 32768u, mb[buf]);
            bulk_cp(xsm + buf * XBUF + 32768, bsrc + ch * 32768, 32768u, mb[buf]);
        }
    };

    float acc[2][8][4];
#pragma unroll
    for (int mf = 0; mf < 2; mf++)
#pragma unroll
        for (int nf = 0; nf < 8; nf++)
#pragma unroll
            for (int i = 0; i < 4; i++) acc[mf][nf][i] = 0.f;

    stage(0, 0);
    stage(1, 1);
    unsigned cnt[2] = {1, 1};

    for (int ch = 0; ch < 8; ch++) {
        int buf = ch & 1;
        mbar_wait(mb[buf], (cnt[buf] - 1) & 1);
        const char* Ab = xsm + buf * XBUF;
        const char* Bb = Ab + 32768;

#pragma unroll
        for (int ks = 0; ks < 4; ks++) {
            unsigned ah[2][4], al[2][4];
#pragma unroll
            for (int mf = 0; mf < 2; mf++) {
                int rh = wm * 32 + mf * 16 + g;
                ah[mf][0] = *(const unsigned*)(Ab + sadr(rh,       ks * 2,     tig));
                ah[mf][2] = *(const unsigned*)(Ab + sadr(rh,       ks * 2 + 1, tig));
                ah[mf][1] = *(const unsigned*)(Ab + sadr(rh + 8,   ks * 2,     tig));
                ah[mf][3] = *(const unsigned*)(Ab + sadr(rh + 8,   ks * 2 + 1, tig));
                al[mf][0] = *(const unsigned*)(Ab + sadr(rh + 128, ks * 2,     tig));
                al[mf][2] = *(const unsigned*)(Ab + sadr(rh + 128, ks * 2 + 1, tig));
                al[mf][1] = *(const unsigned*)(Ab + sadr(rh + 136, ks * 2,     tig));
                al[mf][3] = *(const unsigned*)(Ab + sadr(rh + 136, ks * 2 + 1, tig));
            }
#pragma unroll
            for (int nf = 0; nf < 8; nf++) {
                int rn = wn * 64 + nf * 8 + g;
                unsigned bh0 = *(const unsigned*)(Bb + sadr(rn,       ks * 2,     tig));
                unsigned bh1 = *(const unsigned*)(Bb + sadr(rn,       ks * 2 + 1, tig));
                unsigned bl0 = *(const unsigned*)(Bb + sadr(rn + 128, ks * 2,     tig));
                unsigned bl1 = *(const unsigned*)(Bb + sadr(rn + 128, ks * 2 + 1, tig));
#pragma unroll
                for (int mf = 0; mf < 2; mf++) {
                    mma_bf16(acc[mf][nf], ah[mf][0], ah[mf][1], ah[mf][2], ah[mf][3], bh0, bh1);
                    mma_bf16(acc[mf][nf], ah[mf][0], ah[mf][1], ah[mf][2], ah[mf][3], bl0, bl1);
                    mma_bf16(acc[mf][nf], al[mf][0], al[mf][1], al[mf][2], al[mf][3], bh0, bh1);
                }
            }
        }
        __syncthreads();
        if (ch + 2 < 8) {
            stage(buf, ch + 2);
            cnt[buf]++;
        }
    }

#pragma unroll
    for (int nf = 0; nf < 8; nf++) {
        int col = bn * 128 + wn * 64 + nf * 8 + tig * 2;
        float bb0 = bih[col] + bhh[col];
        float bb1 = bih[col + 1] + bhh[col + 1];
#pragma unroll
        for (int mf = 0; mf < 2; mf++) {
            int row = bm * 128 + wm * 32 + mf * 16 + g;
            *(float2*)(g_xg + (size_t)row * G4 + col) =
                make_float2(acc[mf][nf][0] + bb0, acc[mf][nf][1] + bb1);
            *(float2*)(g_xg + (size_t)(row + 8) * G4 + col) =
                make_float2(acc[mf][nf][2] + bb0, acc[mf][nf][3] + bb1);
        }
    }
}

// ---------------- persistent HMMA LSTM: fragment-order operands ----------------
// SMEM: 8 A-buffers x 8192 = 65536 | W frags 131072 | stash aliases A-buffers
#define SM_WF 65536
#define SM_END (SM_WF + 131072)          // 196608
#define SMEM_BYTES (SM_END + 1024)

__global__ __launch_bounds__(512, 1)
void lstm_tc(const float* __restrict__ Whh, const int* __restrict__ mask,
             const float* __restrict__ h0, const float* __restrict__ c0,
             float* __restrict__ out) {
    extern __shared__ char smraw[];
    char* smb = (char*)(((uintptr_t)smraw + 1023) & ~(uintptr_t)1023);
    char* Wf = smb + SM_WF;                 // fragment-order W: [kblk][ks][nt][plane][lane][8B]
    float* stash = (float*)smb;             // aliases A buffers

    __shared__ __align__(8) unsigned long long mbst[16];   // 0-7 full, 8-15 empty

    int tid = threadIdx.x;
    int w = tid >> 5, lane = tid & 31;
    int g = lane >> 2, tig = lane & 3;
    int wk = w & 3;                          // k-quarter
    int wm4 = w >> 2;                        // row group 0..3
    int bid = blockIdx.x;
    int base = bid * 8;
    int gb_own = base >> 5;
    int eb = tid >> 3, eu = tid & 7;         // epilogue cell (batch row, unit)

    unsigned mbF[2] = { smem_u32(&mbst[wk * 2]),     smem_u32(&mbst[wk * 2 + 1]) };
    unsigned mbE[2] = { smem_u32(&mbst[8 + wk * 2]), smem_u32(&mbst[8 + wk * 2 + 1]) };
    if (tid == 0) {
#pragma unroll
        for (int i = 0; i < 8; i++)  mbar_init(smem_u32(&mbst[i]), 1);
#pragma unroll
        for (int i = 8; i < 16; i++) mbar_init(smem_u32(&mbst[i]), 4);
    }

    // ---- build W fragments once: slot = ((kblk*2+ks)*4 + nt), stride 512 (hi 256 | lo 256) ----
    for (int idx = tid; idx < 8192; idx += 512) {
        int lane_s = idx & 31;
        int slot = idx >> 5;                 // 0..255
        int nt = slot & 3;
        int ks = (slot >> 2) & 1;
        int kblk = slot >> 3;
        int n = nt * 8 + (lane_s >> 2);
        int gate = n >> 3, u = n & 7;
        int k = kblk * 32 + ks * 16 + (lane_s & 3) * 2;
        const float* wr = Whh + ((size_t)(gate * HH + base + u)) * HH;
        float l0, l1, l8, l9;
        unsigned h01 = pack_hi(wr[k], wr[k + 1], l0, l1);
        unsigned h89 = pack_hi(wr[k + 8], wr[k + 9], l8, l9);
        char* dst = Wf + (size_t)slot * 512 + lane_s * 8;
        *(uint2*)dst = make_uint2(h01, h89);
        *(uint2*)(dst + 256) = make_uint2(pack_lo(l0, l1), pack_lo(l8, l9));
    }

    // ---- per-thread state (1 cell) + initial h write (parity 0, fragment order) ----
    float creg = c0[base + eu];
    float hreg = h0[base + eu];
    // fragment-order offset for element (row eb, k-in-block kb)
    int kb0 = (base & 31) + eu;
    int ks0 = kb0 >> 4, c0i = kb0 & 15;
    int rg0 = eb >> 4, r0i = eb & 15;
    int lw = (r0i & 7) * 4 + ((c0i & 7) >> 1);
    int wordi = (r0i >> 3) + 2 * (c0i >> 3);
    unsigned eoff = (unsigned)((rg0 * 4 + ks0) * 512 + lw * 16 + wordi * 4 + (c0i & 1) * 2);
    {
        __nv_bfloat16 hh = __float2bfloat16_rn(hreg);
        float lo = hreg - __bfloat162float(hh);
        __nv_bfloat16 hl = __float2bfloat16_rn(lo);
        unsigned char* blk = g_hA[0] + gb_own * LBLK;
        *(__nv_bfloat16*)(blk + eoff) = hh;
        *(__nv_bfloat16*)(blk + eoff + 1024) = hl;   // lo plane tiles are +2*512
    }
    __syncthreads();
    if (tid == 0) {
        __threadfence();
        atomicAdd(&g_ready[0][gb_own], 1u);
    }

    unsigned ccnt[2] = {0, 0};
    unsigned fcnt[2] = {0, 0};

    for (int t = 0; t < TT; t++) {
        const unsigned char* src = g_hA[t & 3];
        unsigned rdy_target = 4u * (unsigned)(t / 4 + 1);
        const unsigned* rdy = g_ready[t & 3];

        // ---- prologue: warps 0-3 stage their quarter's first two blocks ----
        if (w < 4 && lane == 0) {
#pragma unroll
            for (int d = 0; d < 2; d++) {
                int gb = wk * 8 + d;
                flag_wait(&rdy[gb], rdy_target);
                if (fcnt[d]) mbar_wait(mbE[d], (fcnt[d] - 1) & 1);
                mbar_expect_tx(mbF[d], (unsigned)LBLK);
                bulk_cp(smb + (size_t)(wk * 2 + d) * LBLK, src + (size_t)gb * LBLK, (unsigned)LBLK, mbF[d]);
                fcnt[d]++;
            }
        }

        // ---- prefetch xg + mask (per epilogue cell) ----
        float xg4[4];
        {
            const float* xp = g_xg + ((size_t)eb * TT + t) * G4 + base + eu;
#pragma unroll
            for (int gg = 0; gg < 4; gg++) xg4[gg] = __ldg(xp + gg * HH);
        }
        int m = __ldg(mask + eb * TT + t);

        float acc[4][4];
#pragma unroll
        for (int nt = 0; nt < 4; nt++)
#pragma unroll
            for (int i = 0; i < 4; i++) acc[nt][i] = 0.f;

        // ---- per-quarter K stream ----
        for (int b = 0; b < 8; b++) {
            int d = b & 1;
            mbar_wait(mbF[d], ccnt[d] & 1);
            ccnt[d]++;
            const char* Ab = smb + (size_t)(wk * 2 + d) * LBLK;
            int kblk = wk * 8 + b;

#pragma unroll
            for (int ks = 0; ks < 2; ks++) {
                uint4 AH = *(const uint4*)(Ab + ((wm4 * 4 + ks) << 9) + lane * 16);
                uint4 AL = *(const uint4*)(Ab + ((wm4 * 4 + 2 + ks) << 9) + lane * 16);
#pragma unroll
                for (int nt = 0; nt < 4; nt++) {
                    const char* wf = Wf + ((size_t)((kblk * 2 + ks) * 4 + nt)) * 512 + lane * 8;
                    uint2 BH = *(const uint2*)wf;
                    uint2 BL = *(const uint2*)(wf + 256);
                    mma_bf16(acc[nt], AH.x, AH.y, AH.z, AH.w, BH.x, BH.y);
                    mma_bf16(acc[nt], AH.x, AH.y, AH.z, AH.w, BL.x, BL.y);
                    mma_bf16(acc[nt], AL.x, AL.y, AL.z, AL.w, BH.x, BH.y);
                }
            }

            if (lane == 0) mbar_arrive(mbE[d]);

            if (b + 2 < 8) {
                if (w < 4 && lane == 0) {
                    int gb = wk * 8 + b + 2;
                    flag_wait(&rdy[gb], rdy_target);
                    mbar_wait(mbE[d], (fcnt[d] - 1) & 1);
                    mbar_expect_tx(mbF[d], (unsigned)LBLK);
                    bulk_cp(smb + (size_t)(wk * 2 + d) * LBLK, src + (size_t)gb * LBLK, (unsigned)LBLK, mbF[d]);
                    fcnt[d]++;
                }
            }
        }

        // ---- cross-warp reduction via stash (aliases buffers: sync first) ----
        __syncthreads();
        int rowf = wm4 * 16 + g;
#pragma unroll
        for (int nt = 0; nt < 4; nt++) {
            int c = nt * 8 + tig * 2;
            *(float2*)&stash[((size_t)wk * 64 + rowf) * 34 + c] =
                make_float2(acc[nt][0], acc[nt][1]);
            *(float2*)&stash[((size_t)wk * 64 + rowf + 8) * 34 + c] =
                make_float2(acc[nt][2], acc[nt][3]);
        }
        __syncthreads();

        // ---- epilogue: 1 cell per thread ----
        {
            float gi = xg4[0], gf = xg4[1], gG = xg4[2], go = xg4[3];
#pragma unroll
            for (int ww = 0; ww < 4; ww++) {
                const float* sp = stash + ((size_t)ww * 64 + eb) * 34;
                gi += sp[eu];
                gf += sp[8 + eu];
                gG += sp[16 + eu];
                go += sp[24 + eu];
            }
            float iv = fsigm(gi);
            float fv = fsigm(gf);
            float gv = ftanh(gG);
            float ov = fsigm(go);
            float cn = fv * creg + iv * gv;
            float hn = ov * ftanh(cn);
            creg = m ? cn : creg;
            hn   = m ? hn : hreg;
            hreg = hn;
            out[((size_t)eb * TT + t) * HH + base + eu] = hn;
            __nv_bfloat16 hh = __float2bfloat16_rn(hn);
            float lo = hn - __bfloat162float(hh);
            __nv_bfloat16 hl = __float2bfloat16_rn(lo);
            unsigned char* blk = g_hA[(t + 1) & 3] + gb_own * LBLK;
            *(__nv_bfloat16*)(blk + eoff) = hh;
            *(__nv_bfloat16*)(blk + eoff + 1024) = hl;
        }

        // ---- post readiness of this CTA's slice of h(t+1) ----
        __syncthreads();
        if (tid == 0) {
            __threadfence();
            atomicAdd(&g_ready[(t + 1) & 3][gb_own], 1u);
        }
    }
}

// ---------------- launch ----------------
extern "C" void kernel_launch(void* const* d_in, const int* in_sizes, int n_in,
                              void* d_out, int out_size) {
    const float* x    = (const float*)d_in[0];
    const int*   mask = (const int*)  d_in[1];
    const float* Wih  = (const float*)d_in[2];
    const float* Whh  = (const float*)d_in[3];
    const float* bih  = (const float*)d_in[4];
    const float* bhh  = (const float*)d_in[5];
    const float* h0   = (const float*)d_in[6];
    const float* c0   = (const float*)d_in[7];
    float* out = (float*)d_out;

    cudaFuncSetAttribute(xg_tc, cudaFuncAttributeMaxDynamicSharedMemorySize, XSMEM);
    cudaFuncSetAttribute(lstm_tc, cudaFuncAttributeMaxDynamicSharedMemorySize, SMEM_BYTES);

    z0<<<1, 128>>>();
    cvt<<<(XN8 + WN8 + 255) / 256, 256>>>(x, Wih);
    xg_tc<<<dim3(G4 / 128, (BB * TT) / 128), 256, XSMEM>>>(bih, bhh);
    lstm_tc<<<NBLK, 512, SMEM_BYTES>>>(Whh, mask, h0, c0, out);
}